// round 5
// baseline (speedup 1.0000x reference)
#include <cuda_runtime.h>

// Problem constants
#define B   2
#define D   160
#define H   192
#define W   160
#define HW  (H * W)          // 30720
#define DHW (D * H * W)      // 4915200
#define NVOX (B * DHW)       // 9830400 per channel
#define CH  5
#define WIN 9
#define PAD 4
#define INV_N (1.0f / 729.0f)

// quad (float4) units
#define WQ   (W / 4)         // 40
#define HWQ  (HW / 4)        // 7680
#define DHWQ (DHW / 4)       // 1228800
#define NVOXQ (NVOX / 4)     // 2457600

// H segmentation for k_pass12
#define HSEG  64
#define NSEGH (H / HSEG)     // 3

// D segmentation for k_pass3
#define SEG  8
#define DSEG (D / SEG)       // 20

// Scratch — float4-typed for guaranteed 16B alignment
__device__ float4 g_bufB4[CH * NVOXQ];
__device__ double g_acc[4];           // cc_sum, dx_sum, dy_sum, dz_sum

__device__ __forceinline__ void warp_reduce_atomic(float v, double* dst) {
#pragma unroll
    for (int off = 16; off > 0; off >>= 1)
        v += __shfl_down_sync(0xFFFFFFFFu, v, off);
    if ((threadIdx.x & 31) == 0) atomicAdd(dst, (double)v);
}

__global__ void k_zero() {
    if (threadIdx.x < 4) g_acc[threadIdx.x] = 0.0;
}

// ---------------------------------------------------------------------------
// Fused pass 1+2: products -> 9-tap W box -> 9-tap H box (running window).
__global__ void k_pass12(const float* __restrict__ F, const float* __restrict__ M) {
    __shared__ float sf[W + 2 * PAD];
    __shared__ float sm[W + 2 * PAD];
    __shared__ float ring[WIN][CH][W];          // 28.8 KB

    float* __restrict__ bufB = (float*)g_bufB4;

    const int w = threadIdx.x;
    int blk = blockIdx.x;                        // over B*D*NSEGH = 960
    const int hs = blk % NSEGH; blk /= NSEGH;
    const int d  = blk % D;
    const int b  = blk / D;
    const int h0 = hs * HSEG;

    const size_t plane = (size_t)(b * D + d) * HW;
    const float* __restrict__ Fp = F + plane;
    const float* __restrict__ Mp = M + plane;

    if (w < PAD)     { sf[w] = 0.f;           sm[w] = 0.f; }
    if (w >= W - PAD){ sf[w + 2 * PAD] = 0.f; sm[w + 2 * PAD] = 0.f; }

    float s0 = 0.f, s1 = 0.f, s2 = 0.f, s3 = 0.f, s4 = 0.f;

#define WBOX(r, n0, n1, n2, n3, n4)                                         \
    {                                                                       \
        const bool valid = ((r) >= 0 && (r) < H);                           \
        const float fv_ = valid ? Fp[(r) * W + w] : 0.f;                    \
        const float mv_ = valid ? Mp[(r) * W + w] : 0.f;                    \
        __syncthreads();                                                    \
        sf[w + PAD] = fv_; sm[w + PAD] = mv_;                               \
        __syncthreads();                                                    \
        n0 = 0.f; n1 = 0.f; n2 = 0.f; n3 = 0.f; n4 = 0.f;                   \
        _Pragma("unroll")                                                   \
        for (int k = 0; k < WIN; k++) {                                     \
            const float fk = sf[w + k];                                     \
            const float mk = sm[w + k];                                     \
            n0 += fk; n1 += mk;                                             \
            n2 = fmaf(fk, fk, n2);                                          \
            n3 = fmaf(mk, mk, n3);                                          \
            n4 = fmaf(fk, mk, n4);                                          \
        }                                                                   \
    }

    for (int r = h0 - PAD; r <= h0 + PAD; r++) {
        float n0, n1, n2, n3, n4;
        WBOX(r, n0, n1, n2, n3, n4);
        const int slot = (r + 9) % 9;
        ring[slot][0][w] = n0; ring[slot][1][w] = n1; ring[slot][2][w] = n2;
        ring[slot][3][w] = n3; ring[slot][4][w] = n4;
        s0 += n0; s1 += n1; s2 += n2; s3 += n3; s4 += n4;
    }

    for (int h = h0; h < h0 + HSEG; h++) {
        const size_t o = plane + (size_t)h * W + w;
        bufB[0 * NVOX + o] = s0;
        bufB[1 * NVOX + o] = s1;
        bufB[2 * NVOX + o] = s2;
        bufB[3 * NVOX + o] = s3;
        bufB[4 * NVOX + o] = s4;

        if (h + 1 < h0 + HSEG) {
            const int r = h + 5;
            float n0, n1, n2, n3, n4;
            WBOX(r, n0, n1, n2, n3, n4);
            const int slot = (r + 9) % 9;
            s0 += n0 - ring[slot][0][w]; ring[slot][0][w] = n0;
            s1 += n1 - ring[slot][1][w]; ring[slot][1][w] = n1;
            s2 += n2 - ring[slot][2][w]; ring[slot][2][w] = n2;
            s3 += n3 - ring[slot][3][w]; ring[slot][3][w] = n3;
            s4 += n4 - ring[slot][4][w]; ring[slot][4][w] = n4;
        }
    }
#undef WBOX
}

// ---------------------------------------------------------------------------
// Pass 3 (float4): 9-tap D box (running window) + per-voxel CC + reduction.
// Block = (b, h-quad-group, seg); 160 threads: t -> (h-sub 0..3, w-quad 0..39).
__global__ void k_pass3_cc() {
    const int t = threadIdx.x;
    const int qw = t % WQ;
    const int hs = t / WQ;                   // 0..3
    int blk = blockIdx.x;                    // over B * (H/4) * SEG = 768
    const int seg = blk % SEG; blk /= SEG;
    const int hq = blk % (H / 4);
    const int b  = blk / (H / 4);
    const int h  = hq * 4 + hs;
    const int d0 = seg * DSEG;

    const size_t col = (size_t)b * DHWQ + (size_t)h * WQ + qw;

    float4 s[CH];
#pragma unroll
    for (int c = 0; c < CH; c++) s[c] = make_float4(0.f, 0.f, 0.f, 0.f);

    for (int d = d0 - PAD; d <= d0 + PAD; d++) {
        if (d >= 0 && d < D) {
#pragma unroll
            for (int c = 0; c < CH; c++) {
                const float4 v = g_bufB4[(size_t)c * NVOXQ + col + (size_t)d * HWQ];
                s[c].x += v.x; s[c].y += v.y; s[c].z += v.z; s[c].w += v.w;
            }
        }
    }

    float local = 0.f;
    for (int d = d0; d < d0 + DSEG; d++) {
#define CCC(comp)                                                            \
        {                                                                    \
            const float mf  = s[0].comp * INV_N;                             \
            const float mm  = s[1].comp * INV_N;                             \
            const float vF  = s[2].comp - mf * mf;                           \
            const float vM  = s[3].comp - mm * mm;                           \
            const float cov = s[4].comp - mf * mm;                           \
            local += (cov * cov) / (vF * vM + 1e-8f);                        \
        }
        CCC(x) CCC(y) CCC(z) CCC(w)
#undef CCC

        const int dp = d + PAD + 1;
        const int dm = d - PAD;
        const bool hp = (dp < D), hm = (dm >= 0);
#pragma unroll
        for (int c = 0; c < CH; c++) {
            float4 a = make_float4(0.f, 0.f, 0.f, 0.f);
            float4 u = make_float4(0.f, 0.f, 0.f, 0.f);
            if (hp) a = g_bufB4[(size_t)c * NVOXQ + col + (size_t)dp * HWQ];
            if (hm) u = g_bufB4[(size_t)c * NVOXQ + col + (size_t)dm * HWQ];
            s[c].x += a.x - u.x; s[c].y += a.y - u.y;
            s[c].z += a.z - u.z; s[c].w += a.w - u.w;
        }
    }

    warp_reduce_atomic(local, &g_acc[0]);
}

// ---------------------------------------------------------------------------
// Flow gradient (float4, barrier-free): grid-stride over quads.
#define NF (B * 3 * DHW)     // 29491200
#define NQ (NF / 4)          // 7372800

__global__ void k_grad(const float* __restrict__ flow) {
    const float4* __restrict__ flow4 = (const float4*)flow;
    float sdx = 0.f, sdy = 0.f, sdz = 0.f;
    const int stride = gridDim.x * blockDim.x;

    for (int q = blockIdx.x * blockDim.x + threadIdx.x; q < NQ; q += stride) {
        const float4 v = flow4[q];
        const int w4 = q % WQ;
        int r = q / WQ;
        const int h = r % H; r /= H;
        const int d = r % D;

        // w-diffs (dz)
        sdz += fabsf(v.y - v.x) + fabsf(v.z - v.y) + fabsf(v.w - v.z);
        if (w4 < WQ - 1) sdz += fabsf(flow[4 * q + 4] - v.w);

        if (h < H - 1) {
            const float4 hn = flow4[q + WQ];
            sdx += fabsf(hn.x - v.x) + fabsf(hn.y - v.y)
                 + fabsf(hn.z - v.z) + fabsf(hn.w - v.w);
        }
        if (d < D - 1) {
            const float4 dn = flow4[q + HWQ];
            sdy += fabsf(dn.x - v.x) + fabsf(dn.y - v.y)
                 + fabsf(dn.z - v.z) + fabsf(dn.w - v.w);
        }
    }

    warp_reduce_atomic(sdx, &g_acc[1]);
    warp_reduce_atomic(sdy, &g_acc[2]);
    warp_reduce_atomic(sdz, &g_acc[3]);
}

// ---------------------------------------------------------------------------
__global__ void k_finalize(float* __restrict__ out) {
    const double L_sim = -(g_acc[0] / (double)NVOX);
    const double ndx = (double)B * 3.0 * D * (H - 1) * W;
    const double ndy = (double)B * 3.0 * (D - 1) * H * W;
    const double ndz = (double)B * 3.0 * D * H * (W - 1);
    const double L_reg = g_acc[1] / ndx + g_acc[2] / ndy + g_acc[3] / ndz;
    out[0] = (float)(L_sim + L_reg);
    out[1] = (float)L_sim;
    out[2] = (float)L_reg;
}

// ---------------------------------------------------------------------------
extern "C" void kernel_launch(void* const* d_in, const int* in_sizes, int n_in,
                              void* d_out, int out_size) {
    const float* I_fixed = (const float*)d_in[0];
    const float* I_moved = (const float*)d_in[1];
    const float* flow    = (const float*)d_in[2];
    float* out = (float*)d_out;

    k_zero<<<1, 32>>>();
    k_pass12<<<B * D * NSEGH, W>>>(I_fixed, I_moved);
    k_pass3_cc<<<B * (H / 4) * SEG, 160>>>();
    k_grad<<<2048, 256>>>(flow);
    k_finalize<<<1, 1>>>(out);
}

// round 6
// speedup vs baseline: 1.1872x; 1.1872x over previous
#include <cuda_runtime.h>

// Problem constants
#define B   2
#define D   160
#define H   192
#define W   160
#define HW  (H * W)          // 30720
#define DHW (D * H * W)      // 4915200
#define NVOX (B * DHW)       // 9830400 per channel
#define CH  5
#define WIN 9
#define PAD 4
#define INV_N (1.0f / 729.0f)

// quad (float4) units
#define WQ   (W / 4)         // 40
#define HWQ  (HW / 4)        // 7680
#define DHWQ (DHW / 4)       // 1228800
#define NVOXQ (NVOX / 4)     // 2457600

// H segmentation for k_pass12
#define HSEG  64
#define NSEGH (H / HSEG)     // 3

// D segmentation for k_pass3
#define SEG  8
#define DSEG (D / SEG)       // 20

// D segmentation for k_grad
#define GSEGD 4
#define GDSEG (D / GSEGD)    // 40

// Scratch — float4-typed for guaranteed 16B alignment
__device__ float4 g_bufB4[CH * NVOXQ];
__device__ double g_acc[4];           // cc_sum, dx_sum, dy_sum, dz_sum

__device__ __forceinline__ void warp_reduce_atomic(float v, double* dst) {
#pragma unroll
    for (int off = 16; off > 0; off >>= 1)
        v += __shfl_down_sync(0xFFFFFFFFu, v, off);
    if ((threadIdx.x & 31) == 0) atomicAdd(dst, (double)v);
}

__global__ void k_zero() {
    if (threadIdx.x < 4) g_acc[threadIdx.x] = 0.0;
}

// ---------------------------------------------------------------------------
// Fused pass 1+2: products -> 9-tap W box -> 9-tap H box (running window).
__global__ void k_pass12(const float* __restrict__ F, const float* __restrict__ M) {
    __shared__ float sf[W + 2 * PAD];
    __shared__ float sm[W + 2 * PAD];
    __shared__ float ring[WIN][CH][W];          // 28.8 KB

    float* __restrict__ bufB = (float*)g_bufB4;

    const int w = threadIdx.x;
    int blk = blockIdx.x;                        // over B*D*NSEGH = 960
    const int hs = blk % NSEGH; blk /= NSEGH;
    const int d  = blk % D;
    const int b  = blk / D;
    const int h0 = hs * HSEG;

    const size_t plane = (size_t)(b * D + d) * HW;
    const float* __restrict__ Fp = F + plane;
    const float* __restrict__ Mp = M + plane;

    if (w < PAD)     { sf[w] = 0.f;           sm[w] = 0.f; }
    if (w >= W - PAD){ sf[w + 2 * PAD] = 0.f; sm[w + 2 * PAD] = 0.f; }

    float s0 = 0.f, s1 = 0.f, s2 = 0.f, s3 = 0.f, s4 = 0.f;

#define WBOX(r, n0, n1, n2, n3, n4)                                         \
    {                                                                       \
        const bool valid = ((r) >= 0 && (r) < H);                           \
        const float fv_ = valid ? Fp[(r) * W + w] : 0.f;                    \
        const float mv_ = valid ? Mp[(r) * W + w] : 0.f;                    \
        __syncthreads();                                                    \
        sf[w + PAD] = fv_; sm[w + PAD] = mv_;                               \
        __syncthreads();                                                    \
        n0 = 0.f; n1 = 0.f; n2 = 0.f; n3 = 0.f; n4 = 0.f;                   \
        _Pragma("unroll")                                                   \
        for (int k = 0; k < WIN; k++) {                                     \
            const float fk = sf[w + k];                                     \
            const float mk = sm[w + k];                                     \
            n0 += fk; n1 += mk;                                             \
            n2 = fmaf(fk, fk, n2);                                          \
            n3 = fmaf(mk, mk, n3);                                          \
            n4 = fmaf(fk, mk, n4);                                          \
        }                                                                   \
    }

    for (int r = h0 - PAD; r <= h0 + PAD; r++) {
        float n0, n1, n2, n3, n4;
        WBOX(r, n0, n1, n2, n3, n4);
        const int slot = (r + 9) % 9;
        ring[slot][0][w] = n0; ring[slot][1][w] = n1; ring[slot][2][w] = n2;
        ring[slot][3][w] = n3; ring[slot][4][w] = n4;
        s0 += n0; s1 += n1; s2 += n2; s3 += n3; s4 += n4;
    }

    for (int h = h0; h < h0 + HSEG; h++) {
        const size_t o = plane + (size_t)h * W + w;
        bufB[0 * NVOX + o] = s0;
        bufB[1 * NVOX + o] = s1;
        bufB[2 * NVOX + o] = s2;
        bufB[3 * NVOX + o] = s3;
        bufB[4 * NVOX + o] = s4;

        if (h + 1 < h0 + HSEG) {
            const int r = h + 5;
            float n0, n1, n2, n3, n4;
            WBOX(r, n0, n1, n2, n3, n4);
            const int slot = (r + 9) % 9;
            s0 += n0 - ring[slot][0][w]; ring[slot][0][w] = n0;
            s1 += n1 - ring[slot][1][w]; ring[slot][1][w] = n1;
            s2 += n2 - ring[slot][2][w]; ring[slot][2][w] = n2;
            s3 += n3 - ring[slot][3][w]; ring[slot][3][w] = n3;
            s4 += n4 - ring[slot][4][w]; ring[slot][4][w] = n4;
        }
    }
#undef WBOX
}

// ---------------------------------------------------------------------------
// Pass 3 (float4): 9-tap D box (running window) + per-voxel CC + reduction.
__global__ void k_pass3_cc() {
    const int t = threadIdx.x;
    const int qw = t % WQ;
    const int hs = t / WQ;                   // 0..3
    int blk = blockIdx.x;                    // over B * (H/4) * SEG = 768
    const int seg = blk % SEG; blk /= SEG;
    const int hq = blk % (H / 4);
    const int b  = blk / (H / 4);
    const int h  = hq * 4 + hs;
    const int d0 = seg * DSEG;

    const size_t col = (size_t)b * DHWQ + (size_t)h * WQ + qw;

    float4 s[CH];
#pragma unroll
    for (int c = 0; c < CH; c++) s[c] = make_float4(0.f, 0.f, 0.f, 0.f);

    for (int d = d0 - PAD; d <= d0 + PAD; d++) {
        if (d >= 0 && d < D) {
#pragma unroll
            for (int c = 0; c < CH; c++) {
                const float4 v = g_bufB4[(size_t)c * NVOXQ + col + (size_t)d * HWQ];
                s[c].x += v.x; s[c].y += v.y; s[c].z += v.z; s[c].w += v.w;
            }
        }
    }

    float local = 0.f;
    for (int d = d0; d < d0 + DSEG; d++) {
#define CCC(comp)                                                            \
        {                                                                    \
            const float mf  = s[0].comp * INV_N;                             \
            const float mm  = s[1].comp * INV_N;                             \
            const float vF  = s[2].comp - mf * mf;                           \
            const float vM  = s[3].comp - mm * mm;                           \
            const float cov = s[4].comp - mf * mm;                           \
            local += (cov * cov) / (vF * vM + 1e-8f);                        \
        }
        CCC(x) CCC(y) CCC(z) CCC(w)
#undef CCC

        const int dp = d + PAD + 1;
        const int dm = d - PAD;
        const bool hp = (dp < D), hm = (dm >= 0);
#pragma unroll
        for (int c = 0; c < CH; c++) {
            float4 a = make_float4(0.f, 0.f, 0.f, 0.f);
            float4 u = make_float4(0.f, 0.f, 0.f, 0.f);
            if (hp) a = g_bufB4[(size_t)c * NVOXQ + col + (size_t)dp * HWQ];
            if (hm) u = g_bufB4[(size_t)c * NVOXQ + col + (size_t)dm * HWQ];
            s[c].x += a.x - u.x; s[c].y += a.y - u.y;
            s[c].z += a.z - u.z; s[c].w += a.w - u.w;
        }
    }

    warp_reduce_atomic(local, &g_acc[0]);
}

// ---------------------------------------------------------------------------
// Flow gradient: d-walk with register reuse. Thread owns (b*3+c, h, w-quad)
// column segment; d-neighbor load doubles as next iteration's center quad.
__global__ void k_grad(const float* __restrict__ flow) {
    const float4* __restrict__ f4 = (const float4*)flow;
    const int t = threadIdx.x;
    const int qw = t % WQ;
    const int hs = t / WQ;                   // 0..3
    int blk = blockIdx.x;                    // over B*3 * (H/4) * GSEGD = 1152
    const int seg = blk % GSEGD; blk /= GSEGD;
    const int hq = blk % (H / 4);
    const int bc = blk / (H / 4);            // 0..5 (b*3 + c)
    const int h  = hq * 4 + hs;
    const int d0 = seg * GDSEG;

    const bool hasH = (h < H - 1);
    const bool hasW = (qw < WQ - 1);

    size_t base = (size_t)bc * DHWQ + (size_t)d0 * HWQ + (size_t)h * WQ + qw;
    float sdx = 0.f, sdy = 0.f, sdz = 0.f;
    float4 v = f4[base];

    const int dend = d0 + GDSEG;
#pragma unroll 4
    for (int d = d0; d < dend; d++) {
        sdz += fabsf(v.y - v.x) + fabsf(v.z - v.y) + fabsf(v.w - v.z);
        if (hasW) sdz += fabsf(flow[4 * base + 4] - v.w);
        if (hasH) {
            const float4 hn = f4[base + WQ];
            sdx += fabsf(hn.x - v.x) + fabsf(hn.y - v.y)
                 + fabsf(hn.z - v.z) + fabsf(hn.w - v.w);
        }
        if (d < D - 1) {
            const float4 dn = f4[base + HWQ];
            sdy += fabsf(dn.x - v.x) + fabsf(dn.y - v.y)
                 + fabsf(dn.z - v.z) + fabsf(dn.w - v.w);
            v = dn;
        }
        base += HWQ;
    }

    warp_reduce_atomic(sdx, &g_acc[1]);
    warp_reduce_atomic(sdy, &g_acc[2]);
    warp_reduce_atomic(sdz, &g_acc[3]);
}

// ---------------------------------------------------------------------------
__global__ void k_finalize(float* __restrict__ out) {
    const double L_sim = -(g_acc[0] / (double)NVOX);
    const double ndx = (double)B * 3.0 * D * (H - 1) * W;
    const double ndy = (double)B * 3.0 * (D - 1) * H * W;
    const double ndz = (double)B * 3.0 * D * H * (W - 1);
    const double L_reg = g_acc[1] / ndx + g_acc[2] / ndy + g_acc[3] / ndz;
    out[0] = (float)(L_sim + L_reg);
    out[1] = (float)L_sim;
    out[2] = (float)L_reg;
}

// ---------------------------------------------------------------------------
extern "C" void kernel_launch(void* const* d_in, const int* in_sizes, int n_in,
                              void* d_out, int out_size) {
    const float* I_fixed = (const float*)d_in[0];
    const float* I_moved = (const float*)d_in[1];
    const float* flow    = (const float*)d_in[2];
    float* out = (float*)d_out;

    k_zero<<<1, 32>>>();
    k_pass12<<<B * D * NSEGH, W>>>(I_fixed, I_moved);
    k_pass3_cc<<<B * (H / 4) * SEG, 160>>>();
    k_grad<<<B * 3 * (H / 4) * GSEGD, 160>>>(flow);
    k_finalize<<<1, 1>>>(out);
}

// round 7
// speedup vs baseline: 1.2827x; 1.0804x over previous
#include <cuda_runtime.h>

// Problem constants
#define B   2
#define D   160
#define H   192
#define W   160
#define HW  (H * W)          // 30720
#define DHW (D * H * W)      // 4915200
#define NVOX (B * DHW)       // 9830400 per channel
#define CH  5
#define WIN 9
#define PAD 4
#define INV_N (1.0f / 729.0f)

// quad (float4) units
#define WQ   (W / 4)         // 40
#define HWQ  (HW / 4)        // 7680
#define DHWQ (DHW / 4)       // 1228800
#define NVOXQ (NVOX / 4)     // 2457600

// H segmentation for k_pass12
#define HSEG  64
#define NSEGH (H / HSEG)     // 3

// D segmentation for k_pass3
#define SEG  8
#define DSEG (D / SEG)       // 20

// D segmentation for k_grad
#define GSEGD 4
#define GDSEG (D / GSEGD)    // 40

// Scratch — float4-typed for guaranteed 16B alignment
__device__ float4 g_bufB4[CH * NVOXQ];
__device__ double g_acc[4];           // cc_sum, dx_sum, dy_sum, dz_sum

__device__ __forceinline__ void warp_reduce_atomic(float v, double* dst) {
#pragma unroll
    for (int off = 16; off > 0; off >>= 1)
        v += __shfl_down_sync(0xFFFFFFFFu, v, off);
    if ((threadIdx.x & 31) == 0) atomicAdd(dst, (double)v);
}

__global__ void k_zero() {
    if (threadIdx.x < 4) g_acc[threadIdx.x] = 0.0;
}

// ---------------------------------------------------------------------------
// Fused pass 1+2, chunked: 4 rows staged per barrier (double-buffered).
// Block = (b, d, h-segment); 160 threads = w. 20 barriers/block (was 144).
__global__ void k_pass12(const float* __restrict__ F, const float* __restrict__ M) {
    __shared__ float stg[2][4][2][W + 2 * PAD];  // [buf][row][f/m][w] 10.75KB
    __shared__ float ring[WIN][CH][W];           // 28.8KB

    float* __restrict__ bufB = (float*)g_bufB4;

    const int w = threadIdx.x;
    int blk = blockIdx.x;                        // over B*D*NSEGH = 960
    const int hs = blk % NSEGH; blk /= NSEGH;
    const int d  = blk % D;
    const int b  = blk / D;
    const int h0 = hs * HSEG;

    const size_t plane = (size_t)(b * D + d) * HW;
    const float* __restrict__ Fp = F + plane;
    const float* __restrict__ Mp = M + plane;

    // Zero my ring column (thread-private: no barrier needed for ring ever)
#pragma unroll
    for (int sl = 0; sl < WIN; sl++)
#pragma unroll
        for (int c = 0; c < CH; c++) ring[sl][c][w] = 0.f;

    // Zero staging halos once (interior overwritten every chunk)
    if (w < PAD) {
#pragma unroll
        for (int bu = 0; bu < 2; bu++)
#pragma unroll
            for (int r = 0; r < 4; r++)
#pragma unroll
                for (int c = 0; c < 2; c++) {
                    stg[bu][r][c][w] = 0.f;
                    stg[bu][r][c][w + W + PAD] = 0.f;
                }
    }
    __syncthreads();

    float s0 = 0.f, s1 = 0.f, s2 = 0.f, s3 = 0.f, s4 = 0.f;

    // Stage nr rows starting at r0 into buffer bu (predicated; OOB rows -> 0)
#define STAGE(bu, r0, nr)                                                    \
    {                                                                        \
        _Pragma("unroll")                                                    \
        for (int i = 0; i < (nr); i++) {                                     \
            const int r_ = (r0) + i;                                         \
            const bool valid_ = (r_ >= 0 && r_ < H);                         \
            stg[bu][i][0][w + PAD] = valid_ ? Fp[r_ * W + w] : 0.f;          \
            stg[bu][i][1][w + PAD] = valid_ ? Mp[r_ * W + w] : 0.f;          \
        }                                                                    \
        __syncthreads();                                                     \
    }

    // W-box staged row i of buffer bu (raw row index r), update ring + sums
#define PROC(bu, i, r)                                                       \
    {                                                                        \
        float n0 = 0.f, n1 = 0.f, n2 = 0.f, n3 = 0.f, n4 = 0.f;              \
        _Pragma("unroll")                                                    \
        for (int k = 0; k < WIN; k++) {                                      \
            const float fk = stg[bu][i][0][w + k];                           \
            const float mk = stg[bu][i][1][w + k];                           \
            n0 += fk; n1 += mk;                                              \
            n2 = fmaf(fk, fk, n2);                                           \
            n3 = fmaf(mk, mk, n3);                                           \
            n4 = fmaf(fk, mk, n4);                                           \
        }                                                                    \
        const int slot = ((r) + 18) % 9;                                     \
        s0 += n0 - ring[slot][0][w]; ring[slot][0][w] = n0;                  \
        s1 += n1 - ring[slot][1][w]; ring[slot][1][w] = n1;                  \
        s2 += n2 - ring[slot][2][w]; ring[slot][2][w] = n2;                  \
        s3 += n3 - ring[slot][3][w]; ring[slot][3][w] = n3;                  \
        s4 += n4 - ring[slot][4][w]; ring[slot][4][w] = n4;                  \
    }

#define EMIT(h_)                                                             \
    {                                                                        \
        const size_t o = plane + (size_t)(h_) * W + w;                       \
        bufB[0 * NVOX + o] = s0;                                             \
        bufB[1 * NVOX + o] = s1;                                             \
        bufB[2 * NVOX + o] = s2;                                             \
        bufB[3 * NVOX + o] = s3;                                             \
        bufB[4 * NVOX + o] = s4;                                             \
    }

    // Prologue: rows h0-4 .. h0+4 (9 rows) -> ring + s
    STAGE(0, h0 - 4, 4);
    PROC(0, 0, h0 - 4) PROC(0, 1, h0 - 3) PROC(0, 2, h0 - 2) PROC(0, 3, h0 - 1)
    STAGE(1, h0, 4);
    PROC(1, 0, h0) PROC(1, 1, h0 + 1) PROC(1, 2, h0 + 2) PROC(1, 3, h0 + 3)
    STAGE(0, h0 + 4, 1);
    PROC(0, 0, h0 + 4)

    // Main: 16 chunks of 4 h-outputs, alternating staging buffers (1,0,1,...)
#pragma unroll 1
    for (int ci = 0; ci < HSEG / 4; ci++) {
        const int h = h0 + ci * 4;
        if (ci & 1) {
            STAGE(0, h + 5, 4);
            EMIT(h);
            PROC(0, 0, h + 5) EMIT(h + 1);
            PROC(0, 1, h + 6) EMIT(h + 2);
            PROC(0, 2, h + 7) EMIT(h + 3);
            PROC(0, 3, h + 8)
        } else {
            STAGE(1, h + 5, 4);
            EMIT(h);
            PROC(1, 0, h + 5) EMIT(h + 1);
            PROC(1, 1, h + 6) EMIT(h + 2);
            PROC(1, 2, h + 7) EMIT(h + 3);
            PROC(1, 3, h + 8)
        }
    }
#undef STAGE
#undef PROC
#undef EMIT
}

// ---------------------------------------------------------------------------
// Pass 3 (float4): 9-tap D box (running window) + per-voxel CC + reduction.
__global__ void k_pass3_cc() {
    const int t = threadIdx.x;
    const int qw = t % WQ;
    const int hs = t / WQ;                   // 0..3
    int blk = blockIdx.x;                    // over B * (H/4) * SEG = 768
    const int seg = blk % SEG; blk /= SEG;
    const int hq = blk % (H / 4);
    const int b  = blk / (H / 4);
    const int h  = hq * 4 + hs;
    const int d0 = seg * DSEG;

    const size_t col = (size_t)b * DHWQ + (size_t)h * WQ + qw;

    float4 s[CH];
#pragma unroll
    for (int c = 0; c < CH; c++) s[c] = make_float4(0.f, 0.f, 0.f, 0.f);

    for (int d = d0 - PAD; d <= d0 + PAD; d++) {
        if (d >= 0 && d < D) {
#pragma unroll
            for (int c = 0; c < CH; c++) {
                const float4 v = g_bufB4[(size_t)c * NVOXQ + col + (size_t)d * HWQ];
                s[c].x += v.x; s[c].y += v.y; s[c].z += v.z; s[c].w += v.w;
            }
        }
    }

    float local = 0.f;
    for (int d = d0; d < d0 + DSEG; d++) {
#define CCC(comp)                                                            \
        {                                                                    \
            const float mf  = s[0].comp * INV_N;                             \
            const float mm  = s[1].comp * INV_N;                             \
            const float vF  = s[2].comp - mf * mf;                           \
            const float vM  = s[3].comp - mm * mm;                           \
            const float cov = s[4].comp - mf * mm;                           \
            local += (cov * cov) / (vF * vM + 1e-8f);                        \
        }
        CCC(x) CCC(y) CCC(z) CCC(w)
#undef CCC

        const int dp = d + PAD + 1;
        const int dm = d - PAD;
        const bool hp = (dp < D), hm = (dm >= 0);
#pragma unroll
        for (int c = 0; c < CH; c++) {
            float4 a = make_float4(0.f, 0.f, 0.f, 0.f);
            float4 u = make_float4(0.f, 0.f, 0.f, 0.f);
            if (hp) a = g_bufB4[(size_t)c * NVOXQ + col + (size_t)dp * HWQ];
            if (hm) u = g_bufB4[(size_t)c * NVOXQ + col + (size_t)dm * HWQ];
            s[c].x += a.x - u.x; s[c].y += a.y - u.y;
            s[c].z += a.z - u.z; s[c].w += a.w - u.w;
        }
    }

    warp_reduce_atomic(local, &g_acc[0]);
}

// ---------------------------------------------------------------------------
// Flow gradient: d-walk with register reuse (unchanged from R6 best).
__global__ void k_grad(const float* __restrict__ flow) {
    const float4* __restrict__ f4 = (const float4*)flow;
    const int t = threadIdx.x;
    const int qw = t % WQ;
    const int hs = t / WQ;                   // 0..3
    int blk = blockIdx.x;                    // over B*3 * (H/4) * GSEGD = 1152
    const int seg = blk % GSEGD; blk /= GSEGD;
    const int hq = blk % (H / 4);
    const int bc = blk / (H / 4);            // 0..5 (b*3 + c)
    const int h  = hq * 4 + hs;
    const int d0 = seg * GDSEG;

    const bool hasH = (h < H - 1);
    const bool hasW = (qw < WQ - 1);

    size_t base = (size_t)bc * DHWQ + (size_t)d0 * HWQ + (size_t)h * WQ + qw;
    float sdx = 0.f, sdy = 0.f, sdz = 0.f;
    float4 v = f4[base];

    const int dend = d0 + GDSEG;
#pragma unroll 4
    for (int d = d0; d < dend; d++) {
        sdz += fabsf(v.y - v.x) + fabsf(v.z - v.y) + fabsf(v.w - v.z);
        if (hasW) sdz += fabsf(flow[4 * base + 4] - v.w);
        if (hasH) {
            const float4 hn = f4[base + WQ];
            sdx += fabsf(hn.x - v.x) + fabsf(hn.y - v.y)
                 + fabsf(hn.z - v.z) + fabsf(hn.w - v.w);
        }
        if (d < D - 1) {
            const float4 dn = f4[base + HWQ];
            sdy += fabsf(dn.x - v.x) + fabsf(dn.y - v.y)
                 + fabsf(dn.z - v.z) + fabsf(dn.w - v.w);
            v = dn;
        }
        base += HWQ;
    }

    warp_reduce_atomic(sdx, &g_acc[1]);
    warp_reduce_atomic(sdy, &g_acc[2]);
    warp_reduce_atomic(sdz, &g_acc[3]);
}

// ---------------------------------------------------------------------------
__global__ void k_finalize(float* __restrict__ out) {
    const double L_sim = -(g_acc[0] / (double)NVOX);
    const double ndx = (double)B * 3.0 * D * (H - 1) * W;
    const double ndy = (double)B * 3.0 * (D - 1) * H * W;
    const double ndz = (double)B * 3.0 * D * H * (W - 1);
    const double L_reg = g_acc[1] / ndx + g_acc[2] / ndy + g_acc[3] / ndz;
    out[0] = (float)(L_sim + L_reg);
    out[1] = (float)L_sim;
    out[2] = (float)L_reg;
}

// ---------------------------------------------------------------------------
extern "C" void kernel_launch(void* const* d_in, const int* in_sizes, int n_in,
                              void* d_out, int out_size) {
    const float* I_fixed = (const float*)d_in[0];
    const float* I_moved = (const float*)d_in[1];
    const float* flow    = (const float*)d_in[2];
    float* out = (float*)d_out;

    // One-time host-object creation (streams/events are not device memory).
    static cudaStream_t s_side = 0;
    static cudaEvent_t ev_fork = 0, ev_join = 0;
    if (s_side == 0) {
        cudaStreamCreateWithFlags(&s_side, cudaStreamNonBlocking);
        cudaEventCreateWithFlags(&ev_fork, cudaEventDisableTiming);
        cudaEventCreateWithFlags(&ev_join, cudaEventDisableTiming);
    }

    k_zero<<<1, 32>>>();

    // Fork: k_grad (reads flow only) runs concurrently with pass12/pass3.
    cudaEventRecord(ev_fork, 0);
    cudaStreamWaitEvent(s_side, ev_fork, 0);
    k_grad<<<B * 3 * (H / 4) * GSEGD, 160, 0, s_side>>>(flow);
    cudaEventRecord(ev_join, s_side);

    k_pass12<<<B * D * NSEGH, W>>>(I_fixed, I_moved);
    k_pass3_cc<<<B * (H / 4) * SEG, 160>>>();

    // Join before finalize.
    cudaStreamWaitEvent(0, ev_join, 0);
    k_finalize<<<1, 1>>>(out);
}

// round 8
// speedup vs baseline: 1.4522x; 1.1322x over previous
#include <cuda_runtime.h>

// Problem constants
#define B   2
#define D   160
#define H   192
#define W   160
#define HW  (H * W)          // 30720
#define DHW (D * H * W)      // 4915200
#define NVOX (B * DHW)       // 9830400 per channel
#define CH  5
#define WIN 9
#define PAD 4
#define INV_N (1.0f / 729.0f)

// float2 units (pass3)
#define W2    (W / 2)        // 80
#define HW2   (HW / 2)       // 15360
#define DHW2  (DHW / 2)      // 2457600
#define NVOX2 (NVOX / 2)     // 4915200

// float4 units (grad)
#define WQ   (W / 4)         // 40
#define HWQ  (HW / 4)        // 7680
#define DHWQ (DHW / 4)       // 1228800
#define NVOXQ (NVOX / 4)     // 2457600

// H segmentation for k_pass12
#define HSEG  64
#define NSEGH (H / HSEG)     // 3

// D segmentation for k_pass3 (register-ring version)
#define SEG3  5
#define DSEG3 (D / SEG3)     // 32

// D segmentation for k_grad
#define GSEGD 4
#define GDSEG (D / GSEGD)    // 40

// Scratch — float4-typed for guaranteed 16B alignment
__device__ float4 g_bufB4[CH * NVOXQ];
__device__ double g_acc[4];           // cc_sum, dx_sum, dy_sum, dz_sum

__device__ __forceinline__ void warp_reduce_atomic(float v, double* dst) {
#pragma unroll
    for (int off = 16; off > 0; off >>= 1)
        v += __shfl_down_sync(0xFFFFFFFFu, v, off);
    if ((threadIdx.x & 31) == 0) atomicAdd(dst, (double)v);
}

__global__ void k_zero() {
    if (threadIdx.x < 4) g_acc[threadIdx.x] = 0.0;
}

// ---------------------------------------------------------------------------
// Fused pass 1+2, chunked: 4 rows staged per barrier (double-buffered).
__global__ void k_pass12(const float* __restrict__ F, const float* __restrict__ M) {
    __shared__ float stg[2][4][2][W + 2 * PAD];  // [buf][row][f/m][w]
    __shared__ float ring[WIN][CH][W];

    float* __restrict__ bufB = (float*)g_bufB4;

    const int w = threadIdx.x;
    int blk = blockIdx.x;                        // over B*D*NSEGH = 960
    const int hs = blk % NSEGH; blk /= NSEGH;
    const int d  = blk % D;
    const int b  = blk / D;
    const int h0 = hs * HSEG;

    const size_t plane = (size_t)(b * D + d) * HW;
    const float* __restrict__ Fp = F + plane;
    const float* __restrict__ Mp = M + plane;

#pragma unroll
    for (int sl = 0; sl < WIN; sl++)
#pragma unroll
        for (int c = 0; c < CH; c++) ring[sl][c][w] = 0.f;

    if (w < PAD) {
#pragma unroll
        for (int bu = 0; bu < 2; bu++)
#pragma unroll
            for (int r = 0; r < 4; r++)
#pragma unroll
                for (int c = 0; c < 2; c++) {
                    stg[bu][r][c][w] = 0.f;
                    stg[bu][r][c][w + W + PAD] = 0.f;
                }
    }
    __syncthreads();

    float s0 = 0.f, s1 = 0.f, s2 = 0.f, s3 = 0.f, s4 = 0.f;

#define STAGE(bu, r0, nr)                                                    \
    {                                                                        \
        _Pragma("unroll")                                                    \
        for (int i = 0; i < (nr); i++) {                                     \
            const int r_ = (r0) + i;                                         \
            const bool valid_ = (r_ >= 0 && r_ < H);                         \
            stg[bu][i][0][w + PAD] = valid_ ? Fp[r_ * W + w] : 0.f;          \
            stg[bu][i][1][w + PAD] = valid_ ? Mp[r_ * W + w] : 0.f;          \
        }                                                                    \
        __syncthreads();                                                     \
    }

#define PROC(bu, i, r)                                                       \
    {                                                                        \
        float n0 = 0.f, n1 = 0.f, n2 = 0.f, n3 = 0.f, n4 = 0.f;              \
        _Pragma("unroll")                                                    \
        for (int k = 0; k < WIN; k++) {                                      \
            const float fk = stg[bu][i][0][w + k];                           \
            const float mk = stg[bu][i][1][w + k];                           \
            n0 += fk; n1 += mk;                                              \
            n2 = fmaf(fk, fk, n2);                                           \
            n3 = fmaf(mk, mk, n3);                                           \
            n4 = fmaf(fk, mk, n4);                                           \
        }                                                                    \
        const int slot = ((r) + 18) % 9;                                     \
        s0 += n0 - ring[slot][0][w]; ring[slot][0][w] = n0;                  \
        s1 += n1 - ring[slot][1][w]; ring[slot][1][w] = n1;                  \
        s2 += n2 - ring[slot][2][w]; ring[slot][2][w] = n2;                  \
        s3 += n3 - ring[slot][3][w]; ring[slot][3][w] = n3;                  \
        s4 += n4 - ring[slot][4][w]; ring[slot][4][w] = n4;                  \
    }

#define EMIT(h_)                                                             \
    {                                                                        \
        const size_t o = plane + (size_t)(h_) * W + w;                       \
        bufB[0 * NVOX + o] = s0;                                             \
        bufB[1 * NVOX + o] = s1;                                             \
        bufB[2 * NVOX + o] = s2;                                             \
        bufB[3 * NVOX + o] = s3;                                             \
        bufB[4 * NVOX + o] = s4;                                             \
    }

    STAGE(0, h0 - 4, 4);
    PROC(0, 0, h0 - 4) PROC(0, 1, h0 - 3) PROC(0, 2, h0 - 2) PROC(0, 3, h0 - 1)
    STAGE(1, h0, 4);
    PROC(1, 0, h0) PROC(1, 1, h0 + 1) PROC(1, 2, h0 + 2) PROC(1, 3, h0 + 3)
    STAGE(0, h0 + 4, 1);
    PROC(0, 0, h0 + 4)

#pragma unroll 1
    for (int ci = 0; ci < HSEG / 4; ci++) {
        const int h = h0 + ci * 4;
        if (ci & 1) {
            STAGE(0, h + 5, 4);
            EMIT(h);
            PROC(0, 0, h + 5) EMIT(h + 1);
            PROC(0, 1, h + 6) EMIT(h + 2);
            PROC(0, 2, h + 7) EMIT(h + 3);
            PROC(0, 3, h + 8)
        } else {
            STAGE(1, h + 5, 4);
            EMIT(h);
            PROC(1, 0, h + 5) EMIT(h + 1);
            PROC(1, 1, h + 6) EMIT(h + 2);
            PROC(1, 2, h + 7) EMIT(h + 3);
            PROC(1, 3, h + 8)
        }
    }
#undef STAGE
#undef PROC
#undef EMIT
}

// ---------------------------------------------------------------------------
// Pass 3: register-resident 9-plane D-ring — each bufB element loaded ONCE.
// Thread owns a float2 (h,w) column; fully unrolled d-walk (slot = literal).
__global__ void __launch_bounds__(160) k_pass3_cc() {
    const float2* __restrict__ buf2 = (const float2*)g_bufB4;
    const int t = threadIdx.x;
    const int qw = t % W2;                   // float2 index in row
    const int hs = t / W2;                   // 0..1
    int blk = blockIdx.x;                    // over B * (H/2) * SEG3 = 960
    const int seg = blk % SEG3; blk /= SEG3;
    const int hq = blk % (H / 2);
    const int b  = blk / (H / 2);
    const int h  = hq * 2 + hs;
    const int d0 = seg * DSEG3;

    const size_t col = (size_t)b * DHW2 + (size_t)h * W2 + qw;

    float2 ring[WIN][CH];
    float2 s[CH];
#pragma unroll
    for (int c = 0; c < CH; c++) s[c] = make_float2(0.f, 0.f);

    // Prologue: fill ring with planes d0-4 .. d0+4 (slot i = plane d0-4+i)
#pragma unroll
    for (int i = 0; i < WIN; i++) {
        const int d = d0 - PAD + i;          // d0+4 <= 132 < D always
        const bool v = (d >= 0);
#pragma unroll
        for (int c = 0; c < CH; c++) {
            float2 x = make_float2(0.f, 0.f);
            if (v) x = __ldcs(&buf2[(size_t)c * NVOX2 + col + (size_t)d * HW2]);
            ring[i][c] = x;
            s[c].x += x.x; s[c].y += x.y;
        }
    }

    float local = 0.f;
#pragma unroll
    for (int u = 0; u < DSEG3; u++) {
#define CCC(comp)                                                            \
        {                                                                    \
            const float mf  = s[0].comp * INV_N;                             \
            const float mm  = s[1].comp * INV_N;                             \
            const float vF  = s[2].comp - mf * mf;                           \
            const float vM  = s[3].comp - mm * mm;                           \
            const float cov = s[4].comp - mf * mm;                           \
            local += (cov * cov) / (vF * vM + 1e-8f);                        \
        }
        CCC(x) CCC(y)
#undef CCC

        const int dn = d0 + u + PAD + 1;     // incoming plane
        const int slot = u % 9;              // literal under full unroll
        if (dn < D) {
#pragma unroll
            for (int c = 0; c < CH; c++) {
                const float2 nv = __ldcs(&buf2[(size_t)c * NVOX2 + col + (size_t)dn * HW2]);
                s[c].x += nv.x - ring[slot][c].x;
                s[c].y += nv.y - ring[slot][c].y;
                ring[slot][c] = nv;
            }
        } else {
#pragma unroll
            for (int c = 0; c < CH; c++) {
                s[c].x -= ring[slot][c].x;
                s[c].y -= ring[slot][c].y;
                ring[slot][c] = make_float2(0.f, 0.f);
            }
        }
    }

    warp_reduce_atomic(local, &g_acc[0]);
}

// ---------------------------------------------------------------------------
// Flow gradient: d-walk with register reuse (unchanged, runs on side stream).
__global__ void k_grad(const float* __restrict__ flow) {
    const float4* __restrict__ f4 = (const float4*)flow;
    const int t = threadIdx.x;
    const int qw = t % WQ;
    const int hs = t / WQ;                   // 0..3
    int blk = blockIdx.x;                    // over B*3 * (H/4) * GSEGD = 1152
    const int seg = blk % GSEGD; blk /= GSEGD;
    const int hq = blk % (H / 4);
    const int bc = blk / (H / 4);            // 0..5 (b*3 + c)
    const int h  = hq * 4 + hs;
    const int d0 = seg * GDSEG;

    const bool hasH = (h < H - 1);
    const bool hasW = (qw < WQ - 1);

    size_t base = (size_t)bc * DHWQ + (size_t)d0 * HWQ + (size_t)h * WQ + qw;
    float sdx = 0.f, sdy = 0.f, sdz = 0.f;
    float4 v = f4[base];

    const int dend = d0 + GDSEG;
#pragma unroll 4
    for (int d = d0; d < dend; d++) {
        sdz += fabsf(v.y - v.x) + fabsf(v.z - v.y) + fabsf(v.w - v.z);
        if (hasW) sdz += fabsf(flow[4 * base + 4] - v.w);
        if (hasH) {
            const float4 hn = f4[base + WQ];
            sdx += fabsf(hn.x - v.x) + fabsf(hn.y - v.y)
                 + fabsf(hn.z - v.z) + fabsf(hn.w - v.w);
        }
        if (d < D - 1) {
            const float4 dn = f4[base + HWQ];
            sdy += fabsf(dn.x - v.x) + fabsf(dn.y - v.y)
                 + fabsf(dn.z - v.z) + fabsf(dn.w - v.w);
            v = dn;
        }
        base += HWQ;
    }

    warp_reduce_atomic(sdx, &g_acc[1]);
    warp_reduce_atomic(sdy, &g_acc[2]);
    warp_reduce_atomic(sdz, &g_acc[3]);
}

// ---------------------------------------------------------------------------
__global__ void k_finalize(float* __restrict__ out) {
    const double L_sim = -(g_acc[0] / (double)NVOX);
    const double ndx = (double)B * 3.0 * D * (H - 1) * W;
    const double ndy = (double)B * 3.0 * (D - 1) * H * W;
    const double ndz = (double)B * 3.0 * D * H * (W - 1);
    const double L_reg = g_acc[1] / ndx + g_acc[2] / ndy + g_acc[3] / ndz;
    out[0] = (float)(L_sim + L_reg);
    out[1] = (float)L_sim;
    out[2] = (float)L_reg;
}

// ---------------------------------------------------------------------------
extern "C" void kernel_launch(void* const* d_in, const int* in_sizes, int n_in,
                              void* d_out, int out_size) {
    const float* I_fixed = (const float*)d_in[0];
    const float* I_moved = (const float*)d_in[1];
    const float* flow    = (const float*)d_in[2];
    float* out = (float*)d_out;

    static cudaStream_t s_side = 0;
    static cudaEvent_t ev_fork = 0, ev_join = 0;
    if (s_side == 0) {
        cudaStreamCreateWithFlags(&s_side, cudaStreamNonBlocking);
        cudaEventCreateWithFlags(&ev_fork, cudaEventDisableTiming);
        cudaEventCreateWithFlags(&ev_join, cudaEventDisableTiming);
    }

    k_zero<<<1, 32>>>();

    // Fork: k_grad (reads flow only) runs concurrently with pass12/pass3.
    cudaEventRecord(ev_fork, 0);
    cudaStreamWaitEvent(s_side, ev_fork, 0);
    k_grad<<<B * 3 * (H / 4) * GSEGD, 160, 0, s_side>>>(flow);
    cudaEventRecord(ev_join, s_side);

    k_pass12<<<B * D * NSEGH, W>>>(I_fixed, I_moved);
    k_pass3_cc<<<B * (H / 2) * SEG3, 160>>>();

    cudaStreamWaitEvent(0, ev_join, 0);
    k_finalize<<<1, 1>>>(out);
}